// round 14
// baseline (speedup 1.0000x reference)
#include <cuda_runtime.h>
#include <stdint.h>

#define NN 50000
#define TRUE_E 1600000
#define SCAN_T 1024
#define SCAN_B ((NN + SCAN_T - 1) / SCAN_T)   // 49

// ---------------- scratch (device globals) ----------------
__device__ __align__(16) float g_h1[NN * 128];
__device__ __align__(16) float g_acc1[NN * 128];
__device__ __align__(16) float g_as1[NN * 8];
__device__ __align__(16) float g_ad1[NN * 8];
__device__ __align__(16) float g_sum[128];
__device__ __align__(16) float g_sumsq[128];
__device__ __align__(16) float g_h2[NN * 64];
__device__ __align__(16) float g_as2[NN];
__device__ __align__(16) float g_ad2[NN];
__device__ int g_stride;            // 1 = int32 ids, 2 = int64 ids (lo word)
__device__ int g_done;              // scan inter-block barrier
__device__ int g_deg[NN];
__device__ int g_cursor[NN];
__device__ int g_rowptr[NN + 1];
__device__ int g_bsum[SCAN_B];
__device__ int g_csr[TRUE_E];       // src ids grouped by dst

__device__ __forceinline__ float lrelu(float x) { return fmaxf(x, 0.2f * x); }

__device__ __forceinline__ uint32_t f2tf32(float x) {
    uint32_t u;
    asm("cvt.rna.tf32.f32 %0, %1;" : "=r"(u) : "f"(x));
    return u;
}

__device__ __forceinline__ void mma_tf32(float d[4], uint32_t a0, uint32_t a1,
                                         uint32_t a2, uint32_t a3,
                                         uint32_t b0, uint32_t b1) {
    asm volatile(
        "mma.sync.aligned.m16n8k8.row.col.f32.tf32.tf32.f32 "
        "{%0,%1,%2,%3}, {%4,%5,%6,%7}, {%8,%9}, {%0,%1,%2,%3};"
        : "+f"(d[0]), "+f"(d[1]), "+f"(d[2]), "+f"(d[3])
        : "r"(a0), "r"(a1), "r"(a2), "r"(a3), "r"(b0), "r"(b1));
}

// ---------------- CSR build ----------------
__global__ void zero_deg_kernel(const int* __restrict__ ei) {
    int n = blockIdx.x * blockDim.x + threadIdx.x;
    if (n < NN) g_deg[n] = 0;
    if (n < 128) { g_sum[n] = 0.f; g_sumsq[n] = 0.f; }
    if (n == 1) g_done = 0;
    if (n == 0) {
        int odd_or = 0;
#pragma unroll
        for (int i = 1; i < 64; i += 2) odd_or |= ei[i];
        g_stride = (odd_or == 0) ? 2 : 1;
    }
}

// 2 edges per thread, vectorized for both layouts
__global__ void count_kernel(const int* __restrict__ ei, int E) {
    int idx = blockIdx.x * blockDim.x + threadIdx.x;
    int e2 = idx * 2;
    if (e2 >= E) return;
    int st = g_stride;
    if (st == 1) {
        int2 d = *(const int2*)(ei + TRUE_E + e2);
        atomicAdd(&g_deg[d.x], 1);
        atomicAdd(&g_deg[d.y], 1);
    } else {
        int4 d = *(const int4*)(ei + 2 * TRUE_E + e2 * 2);
        atomicAdd(&g_deg[d.x], 1);
        atomicAdd(&g_deg[d.z], 1);
    }
}

// fused two-phase scan: 49 blocks, inter-block spin barrier (all co-resident)
__global__ void scan_fused() {
    __shared__ int sh[SCAN_T];
    __shared__ int s_bsum[SCAN_B];
    __shared__ int s_boff;
    int tid = threadIdx.x;
    int n = blockIdx.x * SCAN_T + tid;
    int v = (n < NN) ? g_deg[n] : 0;
    sh[tid] = v;
    __syncthreads();
    for (int off = 1; off < SCAN_T; off <<= 1) {
        int t = (tid >= off) ? sh[tid - off] : 0;
        __syncthreads();
        sh[tid] += t;
        __syncthreads();
    }
    if (tid == SCAN_T - 1) {
        g_bsum[blockIdx.x] = sh[SCAN_T - 1];
        __threadfence();
        atomicAdd(&g_done, 1);
    }
    if (tid == 0) {
        while (atomicAdd(&g_done, 0) < (int)gridDim.x) { }
    }
    __syncthreads();
    __threadfence();
    if (tid < SCAN_B) s_bsum[tid] = g_bsum[tid];
    __syncthreads();
    if (tid == 0) {
        int run = 0;
        for (int b = 0; b < (int)blockIdx.x; b++) run += s_bsum[b];
        s_boff = run;
        if (blockIdx.x == gridDim.x - 1) {
            int tot = run;
            for (int b = blockIdx.x; b < SCAN_B; b++) tot += s_bsum[b];
            g_rowptr[NN] = tot;
        }
    }
    __syncthreads();
    if (n < NN) {
        int excl = s_boff + sh[tid] - v;
        g_rowptr[n] = excl;
        g_cursor[n] = excl;
    }
}

__global__ void scatter_kernel(const int* __restrict__ ei, int E) {
    int idx = blockIdx.x * blockDim.x + threadIdx.x;
    int e2 = idx * 2;
    if (e2 >= E) return;
    int st = g_stride;
    int s0, s1, d0, d1;
    if (st == 1) {
        int2 s = *(const int2*)(ei + e2);
        int2 d = *(const int2*)(ei + TRUE_E + e2);
        s0 = s.x; s1 = s.y; d0 = d.x; d1 = d.y;
    } else {
        int4 s = *(const int4*)(ei + e2 * 2);
        int4 d = *(const int4*)(ei + 2 * TRUE_E + e2 * 2);
        s0 = s.x; s1 = s.z; d0 = d.x; d1 = d.z;
    }
    int p0 = atomicAdd(&g_cursor[d0], 1);
    g_csr[p0] = s0;
    int p1 = atomicAdd(&g_cursor[d1], 1);
    g_csr[p1] = s1;
}

// ---------------- tensor-core SGEMM (tf32) + fused alpha epilogue ----------------
template <int BN, bool FUSE_BN, int LAYER>
__global__ void sgemm_tc(const float* __restrict__ Aparam, const float* __restrict__ Bg,
                         const float* __restrict__ av_s, const float* __restrict__ av_d,
                         const float* __restrict__ bng, const float* __restrict__ bnb,
                         int M, int K) {
    const float* __restrict__ A = (LAYER == 1) ? Aparam : (const float*)g_acc1;
    float* __restrict__ C = (LAYER == 1) ? g_h1 : g_h2;

    constexpr int BM = 128, BK = 32;
    constexpr int SA = BK + 4;
    constexpr int SB = BN + 8;
    constexpr int NB = BN / 8;

    __shared__ uint32_t As[BM * SA];
    __shared__ uint32_t Bs[BK * SB];
    __shared__ float s_scale[128], s_shift[128];

    const int tid = threadIdx.x;
    const int lane = tid & 31, warp = tid >> 5;
    const int g = lane >> 2, t = lane & 3;
    const int row0 = blockIdx.x * BM;

    if (FUSE_BN) {
        if (tid < 128) {
            float mu = g_sum[tid] / (float)NN;
            float var = g_sumsq[tid] / (float)NN - mu * mu;
            float rstd = rsqrtf(var + 1e-5f);
            float sc = bng[tid] * rstd;
            s_scale[tid] = sc;
            s_shift[tid] = bnb[tid] - mu * sc;
        }
        __syncthreads();
    }

    float acc[NB][4];
#pragma unroll
    for (int nb = 0; nb < NB; nb++)
#pragma unroll
        for (int q = 0; q < 4; q++) acc[nb][q] = 0.f;

    for (int k0 = 0; k0 < K; k0 += BK) {
#pragma unroll
        for (int f = 0; f < 4; f++) {
            int i = tid + f * 256;
            int r = i >> 3;
            int c4 = (i & 7) * 4;
            float4 v = make_float4(0.f, 0.f, 0.f, 0.f);
            int gr = row0 + r;
            if (gr < M) v = *(const float4*)(A + (size_t)gr * K + k0 + c4);
            if (FUSE_BN) {
                v.x = v.x * s_scale[k0 + c4 + 0] + s_shift[k0 + c4 + 0];
                v.y = v.y * s_scale[k0 + c4 + 1] + s_shift[k0 + c4 + 1];
                v.z = v.z * s_scale[k0 + c4 + 2] + s_shift[k0 + c4 + 2];
                v.w = v.w * s_scale[k0 + c4 + 3] + s_shift[k0 + c4 + 3];
                v.x = v.x > 0.f ? v.x : __expf(v.x) - 1.f;
                v.y = v.y > 0.f ? v.y : __expf(v.y) - 1.f;
                v.z = v.z > 0.f ? v.z : __expf(v.z) - 1.f;
                v.w = v.w > 0.f ? v.w : __expf(v.w) - 1.f;
            }
            uint32_t* p = &As[r * SA + c4];
            p[0] = f2tf32(v.x); p[1] = f2tf32(v.y);
            p[2] = f2tf32(v.z); p[3] = f2tf32(v.w);
        }
        {
            constexpr int BF4 = (BK * BN / 4) / 256;
#pragma unroll
            for (int f = 0; f < BF4; f++) {
                int i = tid + f * 256;
                int r = i / (BN / 4);
                int c4 = (i % (BN / 4)) * 4;
                float4 v = *(const float4*)(Bg + (size_t)(k0 + r) * BN + c4);
                uint32_t* p = &Bs[r * SB + c4];
                p[0] = f2tf32(v.x); p[1] = f2tf32(v.y);
                p[2] = f2tf32(v.z); p[3] = f2tf32(v.w);
            }
        }
        __syncthreads();

#pragma unroll
        for (int k8 = 0; k8 < BK / 8; k8++) {
            int ar = warp * 16 + g;
            uint32_t a0 = As[ar * SA + k8 * 8 + t];
            uint32_t a1 = As[(ar + 8) * SA + k8 * 8 + t];
            uint32_t a2 = As[ar * SA + k8 * 8 + t + 4];
            uint32_t a3 = As[(ar + 8) * SA + k8 * 8 + t + 4];
#pragma unroll
            for (int nb = 0; nb < NB; nb++) {
                uint32_t b0 = Bs[(k8 * 8 + t) * SB + nb * 8 + g];
                uint32_t b1 = Bs[(k8 * 8 + t + 4) * SB + nb * 8 + g];
                mma_tf32(acc[nb], a0, a1, a2, a3, b0, b1);
            }
        }
        __syncthreads();
    }

    int r0 = row0 + warp * 16 + g;
#pragma unroll
    for (int nb = 0; nb < NB; nb++) {
        int cc = nb * 8 + 2 * t;
        if (r0 < M)
            *(float2*)(C + (size_t)r0 * BN + cc) = make_float2(acc[nb][0], acc[nb][1]);
        if (r0 + 8 < M)
            *(float2*)(C + (size_t)(r0 + 8) * BN + cc) = make_float2(acc[nb][2], acc[nb][3]);
    }

    if (LAYER == 1) {
#pragma unroll
        for (int h = 0; h < 8; h++) {
            int cA = 16 * h + 2 * t;
            int cB = cA + 8;
            float sA0 = __ldg(av_s + cA), sA1 = __ldg(av_s + cA + 1);
            float sB0 = __ldg(av_s + cB), sB1 = __ldg(av_s + cB + 1);
            float dA0 = __ldg(av_d + cA), dA1 = __ldg(av_d + cA + 1);
            float dB0 = __ldg(av_d + cB), dB1 = __ldg(av_d + cB + 1);
            float ss0 = acc[2*h][0]*sA0 + acc[2*h][1]*sA1 + acc[2*h+1][0]*sB0 + acc[2*h+1][1]*sB1;
            float sd0 = acc[2*h][0]*dA0 + acc[2*h][1]*dA1 + acc[2*h+1][0]*dB0 + acc[2*h+1][1]*dB1;
            float ss8 = acc[2*h][2]*sA0 + acc[2*h][3]*sA1 + acc[2*h+1][2]*sB0 + acc[2*h+1][3]*sB1;
            float sd8 = acc[2*h][2]*dA0 + acc[2*h][3]*dA1 + acc[2*h+1][2]*dB0 + acc[2*h+1][3]*dB1;
            ss0 += __shfl_xor_sync(0xffffffffu, ss0, 1); ss0 += __shfl_xor_sync(0xffffffffu, ss0, 2);
            sd0 += __shfl_xor_sync(0xffffffffu, sd0, 1); sd0 += __shfl_xor_sync(0xffffffffu, sd0, 2);
            ss8 += __shfl_xor_sync(0xffffffffu, ss8, 1); ss8 += __shfl_xor_sync(0xffffffffu, ss8, 2);
            sd8 += __shfl_xor_sync(0xffffffffu, sd8, 1); sd8 += __shfl_xor_sync(0xffffffffu, sd8, 2);
            if (t == 0) {
                if (r0 < M)     { g_as1[r0 * 8 + h] = ss0;       g_ad1[r0 * 8 + h] = sd0; }
                if (r0 + 8 < M) { g_as1[(r0 + 8) * 8 + h] = ss8; g_ad1[(r0 + 8) * 8 + h] = sd8; }
            }
        }
    } else {
        float ss0 = 0.f, sd0 = 0.f, ss8 = 0.f, sd8 = 0.f;
#pragma unroll
        for (int nb = 0; nb < NB; nb++) {
            int cc = nb * 8 + 2 * t;
            float s0 = __ldg(av_s + cc), s1 = __ldg(av_s + cc + 1);
            float d0 = __ldg(av_d + cc), d1 = __ldg(av_d + cc + 1);
            ss0 += acc[nb][0] * s0 + acc[nb][1] * s1;
            sd0 += acc[nb][0] * d0 + acc[nb][1] * d1;
            ss8 += acc[nb][2] * s0 + acc[nb][3] * s1;
            sd8 += acc[nb][2] * d0 + acc[nb][3] * d1;
        }
        ss0 += __shfl_xor_sync(0xffffffffu, ss0, 1); ss0 += __shfl_xor_sync(0xffffffffu, ss0, 2);
        sd0 += __shfl_xor_sync(0xffffffffu, sd0, 1); sd0 += __shfl_xor_sync(0xffffffffu, sd0, 2);
        ss8 += __shfl_xor_sync(0xffffffffu, ss8, 1); ss8 += __shfl_xor_sync(0xffffffffu, ss8, 2);
        sd8 += __shfl_xor_sync(0xffffffffu, sd8, 1); sd8 += __shfl_xor_sync(0xffffffffu, sd8, 2);
        if (t == 0) {
            if (r0 < M)     { g_as2[r0] = ss0;     g_ad2[r0] = sd0; }
            if (r0 + 8 < M) { g_as2[r0 + 8] = ss8; g_ad2[r0 + 8] = sd8; }
        }
    }
}

// ---------------- layer 1 aggregation: warp per node, 4x pipelined ----------------
__global__ void agg1_kernel(const float* __restrict__ b1) {
    __shared__ float bsum[128], bssq[128];
    int tid = threadIdx.x;
    if (tid < 128) { bsum[tid] = 0.f; bssq[tid] = 0.f; }
    __syncthreads();

    int lane = tid & 31, wid = tid >> 5;
    int h = lane >> 2, c4 = lane * 4;
    float4 bias = *(const float4*)(b1 + c4);
    float4 psum = make_float4(0.f, 0.f, 0.f, 0.f);
    float4 pssq = make_float4(0.f, 0.f, 0.f, 0.f);

    for (int n = blockIdx.x * 8 + wid; n < NN; n += gridDim.x * 8) {
        float ad_h = __ldg(g_ad1 + n * 8 + h);
        float4 hv = *(const float4*)(g_h1 + (size_t)n * 128 + c4);
        float w = __expf(lrelu(__ldg(g_as1 + n * 8 + h) + ad_h));
        float ax = w * hv.x, ay = w * hv.y, az = w * hv.z, aw = w * hv.w;
        float den = w;
        int beg = g_rowptr[n], end = g_rowptr[n + 1];
        int j = beg;
        for (; j + 3 < end; j += 4) {
            int s0 = __ldg(g_csr + j),     s1 = __ldg(g_csr + j + 1);
            int s2 = __ldg(g_csr + j + 2), s3 = __ldg(g_csr + j + 3);
            float a0 = __ldg(g_as1 + (size_t)s0 * 8 + h);
            float a1 = __ldg(g_as1 + (size_t)s1 * 8 + h);
            float a2 = __ldg(g_as1 + (size_t)s2 * 8 + h);
            float a3 = __ldg(g_as1 + (size_t)s3 * 8 + h);
            float4 h0 = *(const float4*)(g_h1 + (size_t)s0 * 128 + c4);
            float4 h1v = *(const float4*)(g_h1 + (size_t)s1 * 128 + c4);
            float4 h2v = *(const float4*)(g_h1 + (size_t)s2 * 128 + c4);
            float4 h3v = *(const float4*)(g_h1 + (size_t)s3 * 128 + c4);
            float e0 = __expf(lrelu(a0 + ad_h));
            float e1 = __expf(lrelu(a1 + ad_h));
            float e2 = __expf(lrelu(a2 + ad_h));
            float e3 = __expf(lrelu(a3 + ad_h));
            ax += e0 * h0.x + e1 * h1v.x + e2 * h2v.x + e3 * h3v.x;
            ay += e0 * h0.y + e1 * h1v.y + e2 * h2v.y + e3 * h3v.y;
            az += e0 * h0.z + e1 * h1v.z + e2 * h2v.z + e3 * h3v.z;
            aw += e0 * h0.w + e1 * h1v.w + e2 * h2v.w + e3 * h3v.w;
            den += (e0 + e1) + (e2 + e3);
        }
        for (; j < end; j++) {
            int s = __ldg(g_csr + j);
            float ee = __expf(lrelu(__ldg(g_as1 + (size_t)s * 8 + h) + ad_h));
            float4 hs = *(const float4*)(g_h1 + (size_t)s * 128 + c4);
            ax += ee * hs.x; ay += ee * hs.y; az += ee * hs.z; aw += ee * hs.w;
            den += ee;
        }
        float inv = 1.f / den;
        float4 v = make_float4(ax * inv + bias.x, ay * inv + bias.y,
                               az * inv + bias.z, aw * inv + bias.w);
        *(float4*)(g_acc1 + (size_t)n * 128 + c4) = v;
        psum.x += v.x; psum.y += v.y; psum.z += v.z; psum.w += v.w;
        pssq.x += v.x * v.x; pssq.y += v.y * v.y; pssq.z += v.z * v.z; pssq.w += v.w * v.w;
    }

    atomicAdd(&bsum[c4 + 0], psum.x); atomicAdd(&bsum[c4 + 1], psum.y);
    atomicAdd(&bsum[c4 + 2], psum.z); atomicAdd(&bsum[c4 + 3], psum.w);
    atomicAdd(&bssq[c4 + 0], pssq.x); atomicAdd(&bssq[c4 + 1], pssq.y);
    atomicAdd(&bssq[c4 + 2], pssq.z); atomicAdd(&bssq[c4 + 3], pssq.w);
    __syncthreads();
    if (tid < 128) {
        atomicAdd(&g_sum[tid], bsum[tid]);
        atomicAdd(&g_sumsq[tid], bssq[tid]);
    }
}

// ---------------- layer 2 aggregation: warp per node, 8x pipelined ----------------
__global__ void agg2_kernel(float* __restrict__ out, const float* __restrict__ b2) {
    int tid = threadIdx.x;
    int lane = tid & 31, wid = tid >> 5;
    int c2 = lane * 2;
    float2 bias = *(const float2*)(b2 + c2);

    for (int n = blockIdx.x * 8 + wid; n < NN; n += gridDim.x * 8) {
        float adn = __ldg(g_ad2 + n);
        float2 hv = *(const float2*)(g_h2 + (size_t)n * 64 + c2);
        float w = __expf(lrelu(__ldg(g_as2 + n) + adn));
        float ax = w * hv.x, ay = w * hv.y;
        float den = w;
        int beg = g_rowptr[n], end = g_rowptr[n + 1];
        int j = beg;
        for (; j + 7 < end; j += 8) {
            int s0 = __ldg(g_csr + j),     s1 = __ldg(g_csr + j + 1);
            int s2 = __ldg(g_csr + j + 2), s3 = __ldg(g_csr + j + 3);
            int s4 = __ldg(g_csr + j + 4), s5 = __ldg(g_csr + j + 5);
            int s6 = __ldg(g_csr + j + 6), s7 = __ldg(g_csr + j + 7);
            float a0 = __ldg(g_as2 + s0), a1 = __ldg(g_as2 + s1);
            float a2 = __ldg(g_as2 + s2), a3 = __ldg(g_as2 + s3);
            float a4 = __ldg(g_as2 + s4), a5 = __ldg(g_as2 + s5);
            float a6 = __ldg(g_as2 + s6), a7 = __ldg(g_as2 + s7);
            float2 h0 = *(const float2*)(g_h2 + (size_t)s0 * 64 + c2);
            float2 h1v = *(const float2*)(g_h2 + (size_t)s1 * 64 + c2);
            float2 h2v = *(const float2*)(g_h2 + (size_t)s2 * 64 + c2);
            float2 h3v = *(const float2*)(g_h2 + (size_t)s3 * 64 + c2);
            float2 h4v = *(const float2*)(g_h2 + (size_t)s4 * 64 + c2);
            float2 h5v = *(const float2*)(g_h2 + (size_t)s5 * 64 + c2);
            float2 h6v = *(const float2*)(g_h2 + (size_t)s6 * 64 + c2);
            float2 h7v = *(const float2*)(g_h2 + (size_t)s7 * 64 + c2);
            float e0 = __expf(lrelu(a0 + adn));
            float e1 = __expf(lrelu(a1 + adn));
            float e2 = __expf(lrelu(a2 + adn));
            float e3 = __expf(lrelu(a3 + adn));
            float e4 = __expf(lrelu(a4 + adn));
            float e5 = __expf(lrelu(a5 + adn));
            float e6 = __expf(lrelu(a6 + adn));
            float e7 = __expf(lrelu(a7 + adn));
            ax += e0 * h0.x + e1 * h1v.x + e2 * h2v.x + e3 * h3v.x
                + e4 * h4v.x + e5 * h5v.x + e6 * h6v.x + e7 * h7v.x;
            ay += e0 * h0.y + e1 * h1v.y + e2 * h2v.y + e3 * h3v.y
                + e4 * h4v.y + e5 * h5v.y + e6 * h6v.y + e7 * h7v.y;
            den += ((e0 + e1) + (e2 + e3)) + ((e4 + e5) + (e6 + e7));
        }
        for (; j < end; j++) {
            int s = __ldg(g_csr + j);
            float ee = __expf(lrelu(__ldg(g_as2 + s) + adn));
            float2 hs = *(const float2*)(g_h2 + (size_t)s * 64 + c2);
            ax += ee * hs.x; ay += ee * hs.y;
            den += ee;
        }
        float inv = 1.f / den;
        *(float2*)(out + (size_t)n * 64 + c2) =
            make_float2(ax * inv + bias.x, ay * inv + bias.y);
    }
}

// ---------------- launch ----------------
extern "C" void kernel_launch(void* const* d_in, const int* in_sizes, int n_in,
                              void* d_out, int out_size) {
    // ---- size-driven input resolution (insertion OR alphabetical order) ----
    int iW1 = -1, iW2 = -1, ibig[2] = {-1, -1}, nbig = 0;
    int i128[8], n128 = 0, i64v[8], n64 = 0;
    for (int i = 0; i < n_in; i++) {
        int s = in_sizes[i];
        if (s == 16384)            iW1 = i;
        else if (s == 8192)        iW2 = i;
        else if (s >= 3000000)   { if (nbig < 2) ibig[nbig] = i; nbig++; }
        else if (s == 128)       { if (n128 < 8) i128[n128] = i; n128++; }
        else if (s == 64)        { if (n64  < 8) i64v[n64]  = i; n64++;  }
    }
    const bool insertion = (ibig[0] >= 0 && iW1 >= 0 && ibig[0] < iW1);

    int ix, iei, ia1s, ia1d, ib1, ibng, ibnb, ia2s, ia2d, ib2;
    if (insertion) {
        ix = ibig[0]; iei = ibig[1];
        ia1s = i128[0]; ia1d = i128[1]; ib1 = i128[2]; ibng = i128[3]; ibnb = i128[4];
        ia2s = i64v[0]; ia2d = i64v[1]; ib2 = i64v[2];
    } else {
        iei = ibig[0]; ix = ibig[1];
        ia1d = i128[0]; ia1s = i128[1]; ib1 = i128[2]; ibnb = i128[3]; ibng = i128[4];
        ia2d = i64v[0]; ia2s = i64v[1]; ib2 = i64v[2];
    }
    if (nbig == 2 && in_sizes[ibig[0]] != in_sizes[ibig[1]]) {
        if (in_sizes[iei] > in_sizes[ix]) { int t = ix; ix = iei; iei = t; }
    }

    const float* x    = (const float*)d_in[ix];
    const int*   ei   = (const int*)d_in[iei];
    const float* W1   = (const float*)d_in[iW1];
    const float* a1s  = (const float*)d_in[ia1s];
    const float* a1d  = (const float*)d_in[ia1d];
    const float* b1   = (const float*)d_in[ib1];
    const float* bng  = (const float*)d_in[ibng];
    const float* bnb  = (const float*)d_in[ibnb];
    const float* W2   = (const float*)d_in[iW2];
    const float* a2s  = (const float*)d_in[ia2s];
    const float* a2d  = (const float*)d_in[ia2d];
    const float* b2   = (const float*)d_in[ib2];
    float* out = (float*)d_out;

    const int E = TRUE_E;
    const int T = 256;
    dim3 blk(T);
    const int AGG_BLOCKS = 592;
    const int GEMM_BLOCKS = (NN + 127) / 128;
    const int EDGE2_BLOCKS = (E / 2 + T - 1) / T;

    cudaStream_t s2;
    cudaStreamCreate(&s2);
    cudaEvent_t evF, evJ;
    cudaEventCreate(&evF);
    cudaEventCreate(&evJ);

    cudaEventRecord(evF, 0);
    cudaStreamWaitEvent(s2, evF, 0);

    // default stream: CSR chain
    zero_deg_kernel<<<(NN + T - 1) / T, blk>>>(ei);
    count_kernel<<<EDGE2_BLOCKS, blk>>>(ei, E);
    scan_fused<<<SCAN_B, SCAN_T>>>();
    scatter_kernel<<<EDGE2_BLOCKS, blk>>>(ei, E);

    // s2: layer-1 GEMM with fused alpha
    sgemm_tc<128, false, 1><<<GEMM_BLOCKS, blk, 0, s2>>>(x, W1, a1s, a1d, nullptr, nullptr, NN, 128);
    cudaEventRecord(evJ, s2);
    cudaStreamWaitEvent(0, evJ, 0);

    // join
    agg1_kernel<<<AGG_BLOCKS, blk>>>(b1);
    sgemm_tc<64, true, 2><<<GEMM_BLOCKS, blk>>>(nullptr, W2, a2s, a2d, bng, bnb, NN, 128);
    agg2_kernel<<<AGG_BLOCKS, blk>>>(out, b2);
}

// round 15
// speedup vs baseline: 1.1669x; 1.1669x over previous
#include <cuda_runtime.h>
#include <stdint.h>

#define NN 50000
#define TRUE_E 1600000
#define SCAN_T 1024
#define SCAN_B ((NN + SCAN_T - 1) / SCAN_T)   // 49

// ---------------- scratch (device globals) ----------------
__device__ __align__(16) float g_h1[NN * 128];
__device__ __align__(16) float g_acc1[NN * 128];
__device__ __align__(16) float g_as1[NN * 8];
__device__ __align__(16) float g_ad1[NN * 8];
__device__ __align__(16) float g_sum[128];
__device__ __align__(16) float g_sumsq[128];
__device__ __align__(16) float g_h2[NN * 64];
__device__ __align__(16) float g_as2[NN];
__device__ __align__(16) float g_ad2[NN];
__device__ int g_stride;            // 1 = int32 ids, 2 = int64 ids (lo word)
__device__ int g_done;              // scan inter-block barrier
__device__ int g_deg[NN];
__device__ int g_cursor[NN];
__device__ int g_rowptr[NN + 1];
__device__ int g_bsum[SCAN_B];
__device__ int g_csr[TRUE_E];       // src ids grouped by dst

__device__ __forceinline__ float lrelu(float x) { return fmaxf(x, 0.2f * x); }

__device__ __forceinline__ uint32_t f2tf32(float x) {
    uint32_t u;
    asm("cvt.rna.tf32.f32 %0, %1;" : "=r"(u) : "f"(x));
    return u;
}

__device__ __forceinline__ void mma_tf32(float d[4], uint32_t a0, uint32_t a1,
                                         uint32_t a2, uint32_t a3,
                                         uint32_t b0, uint32_t b1) {
    asm volatile(
        "mma.sync.aligned.m16n8k8.row.col.f32.tf32.tf32.f32 "
        "{%0,%1,%2,%3}, {%4,%5,%6,%7}, {%8,%9}, {%0,%1,%2,%3};"
        : "+f"(d[0]), "+f"(d[1]), "+f"(d[2]), "+f"(d[3])
        : "r"(a0), "r"(a1), "r"(a2), "r"(a3), "r"(b0), "r"(b1));
}

__device__ __forceinline__ void edge_ids(const int* ei, int e, int st, int& s, int& d) {
    s = ei[(size_t)e * st];
    d = ei[(size_t)st * TRUE_E + (size_t)e * st];
}

// ---------------- CSR build ----------------
__global__ void zero_deg_kernel(const int* __restrict__ ei) {
    int n = blockIdx.x * blockDim.x + threadIdx.x;
    if (n < NN) g_deg[n] = 0;
    if (n < 128) { g_sum[n] = 0.f; g_sumsq[n] = 0.f; }
    if (n == 1) g_done = 0;
    if (n == 0) {
        int odd_or = 0;
#pragma unroll
        for (int i = 1; i < 64; i += 2) odd_or |= ei[i];
        g_stride = (odd_or == 0) ? 2 : 1;
    }
}

__global__ void count_kernel(const int* __restrict__ ei, int E) {
    int e = blockIdx.x * blockDim.x + threadIdx.x;
    if (e >= E) return;
    int st = g_stride;
    int d = ei[(size_t)st * TRUE_E + (size_t)e * st];
    atomicAdd(&g_deg[d], 1);
}

// fused two-phase scan: 49 blocks, inter-block spin barrier (all co-resident)
__global__ void scan_fused() {
    __shared__ int sh[SCAN_T];
    __shared__ int s_bsum[SCAN_B];
    __shared__ int s_boff;
    int tid = threadIdx.x;
    int n = blockIdx.x * SCAN_T + tid;
    int v = (n < NN) ? g_deg[n] : 0;
    sh[tid] = v;
    __syncthreads();
    for (int off = 1; off < SCAN_T; off <<= 1) {
        int t = (tid >= off) ? sh[tid - off] : 0;
        __syncthreads();
        sh[tid] += t;
        __syncthreads();
    }
    if (tid == SCAN_T - 1) {
        g_bsum[blockIdx.x] = sh[SCAN_T - 1];
        __threadfence();
        atomicAdd(&g_done, 1);
    }
    if (tid == 0) {
        while (atomicAdd(&g_done, 0) < (int)gridDim.x) { }
    }
    __syncthreads();
    __threadfence();
    if (tid < SCAN_B) s_bsum[tid] = g_bsum[tid];
    __syncthreads();
    if (tid == 0) {
        int run = 0;
        for (int b = 0; b < (int)blockIdx.x; b++) run += s_bsum[b];
        s_boff = run;
        if (blockIdx.x == gridDim.x - 1) {
            int tot = run;
            for (int b = blockIdx.x; b < SCAN_B; b++) tot += s_bsum[b];
            g_rowptr[NN] = tot;
        }
    }
    __syncthreads();
    if (n < NN) {
        int excl = s_boff + sh[tid] - v;
        g_rowptr[n] = excl;
        g_cursor[n] = excl;
    }
}

__global__ void scatter_kernel(const int* __restrict__ ei, int E) {
    int e = blockIdx.x * blockDim.x + threadIdx.x;
    if (e >= E) return;
    int st = g_stride, s, d;
    edge_ids(ei, e, st, s, d);
    int pos = atomicAdd(&g_cursor[d], 1);
    g_csr[pos] = s;
}

// ---------------- tensor-core SGEMM (tf32) + fused alpha epilogue ----------------
template <int BN, bool FUSE_BN, int LAYER>
__global__ void sgemm_tc(const float* __restrict__ Aparam, const float* __restrict__ Bg,
                         const float* __restrict__ av_s, const float* __restrict__ av_d,
                         const float* __restrict__ bng, const float* __restrict__ bnb,
                         int M, int K) {
    const float* __restrict__ A = (LAYER == 1) ? Aparam : (const float*)g_acc1;
    float* __restrict__ C = (LAYER == 1) ? g_h1 : g_h2;

    constexpr int BM = 128, BK = 32;
    constexpr int SA = BK + 4;
    constexpr int SB = BN + 8;
    constexpr int NB = BN / 8;

    __shared__ uint32_t As[BM * SA];
    __shared__ uint32_t Bs[BK * SB];
    __shared__ float s_scale[128], s_shift[128];

    const int tid = threadIdx.x;
    const int lane = tid & 31, warp = tid >> 5;
    const int g = lane >> 2, t = lane & 3;
    const int row0 = blockIdx.x * BM;

    if (FUSE_BN) {
        if (tid < 128) {
            float mu = g_sum[tid] / (float)NN;
            float var = g_sumsq[tid] / (float)NN - mu * mu;
            float rstd = rsqrtf(var + 1e-5f);
            float sc = bng[tid] * rstd;
            s_scale[tid] = sc;
            s_shift[tid] = bnb[tid] - mu * sc;
        }
        __syncthreads();
    }

    float acc[NB][4];
#pragma unroll
    for (int nb = 0; nb < NB; nb++)
#pragma unroll
        for (int q = 0; q < 4; q++) acc[nb][q] = 0.f;

    for (int k0 = 0; k0 < K; k0 += BK) {
#pragma unroll
        for (int f = 0; f < 4; f++) {
            int i = tid + f * 256;
            int r = i >> 3;
            int c4 = (i & 7) * 4;
            float4 v = make_float4(0.f, 0.f, 0.f, 0.f);
            int gr = row0 + r;
            if (gr < M) v = *(const float4*)(A + (size_t)gr * K + k0 + c4);
            if (FUSE_BN) {
                v.x = v.x * s_scale[k0 + c4 + 0] + s_shift[k0 + c4 + 0];
                v.y = v.y * s_scale[k0 + c4 + 1] + s_shift[k0 + c4 + 1];
                v.z = v.z * s_scale[k0 + c4 + 2] + s_shift[k0 + c4 + 2];
                v.w = v.w * s_scale[k0 + c4 + 3] + s_shift[k0 + c4 + 3];
                v.x = v.x > 0.f ? v.x : __expf(v.x) - 1.f;
                v.y = v.y > 0.f ? v.y : __expf(v.y) - 1.f;
                v.z = v.z > 0.f ? v.z : __expf(v.z) - 1.f;
                v.w = v.w > 0.f ? v.w : __expf(v.w) - 1.f;
            }
            uint32_t* p = &As[r * SA + c4];
            p[0] = f2tf32(v.x); p[1] = f2tf32(v.y);
            p[2] = f2tf32(v.z); p[3] = f2tf32(v.w);
        }
        {
            constexpr int BF4 = (BK * BN / 4) / 256;
#pragma unroll
            for (int f = 0; f < BF4; f++) {
                int i = tid + f * 256;
                int r = i / (BN / 4);
                int c4 = (i % (BN / 4)) * 4;
                float4 v = *(const float4*)(Bg + (size_t)(k0 + r) * BN + c4);
                uint32_t* p = &Bs[r * SB + c4];
                p[0] = f2tf32(v.x); p[1] = f2tf32(v.y);
                p[2] = f2tf32(v.z); p[3] = f2tf32(v.w);
            }
        }
        __syncthreads();

#pragma unroll
        for (int k8 = 0; k8 < BK / 8; k8++) {
            int ar = warp * 16 + g;
            uint32_t a0 = As[ar * SA + k8 * 8 + t];
            uint32_t a1 = As[(ar + 8) * SA + k8 * 8 + t];
            uint32_t a2 = As[ar * SA + k8 * 8 + t + 4];
            uint32_t a3 = As[(ar + 8) * SA + k8 * 8 + t + 4];
#pragma unroll
            for (int nb = 0; nb < NB; nb++) {
                uint32_t b0 = Bs[(k8 * 8 + t) * SB + nb * 8 + g];
                uint32_t b1 = Bs[(k8 * 8 + t + 4) * SB + nb * 8 + g];
                mma_tf32(acc[nb], a0, a1, a2, a3, b0, b1);
            }
        }
        __syncthreads();
    }

    int r0 = row0 + warp * 16 + g;
#pragma unroll
    for (int nb = 0; nb < NB; nb++) {
        int cc = nb * 8 + 2 * t;
        if (r0 < M)
            *(float2*)(C + (size_t)r0 * BN + cc) = make_float2(acc[nb][0], acc[nb][1]);
        if (r0 + 8 < M)
            *(float2*)(C + (size_t)(r0 + 8) * BN + cc) = make_float2(acc[nb][2], acc[nb][3]);
    }

    if (LAYER == 1) {
#pragma unroll
        for (int h = 0; h < 8; h++) {
            int cA = 16 * h + 2 * t;
            int cB = cA + 8;
            float sA0 = __ldg(av_s + cA), sA1 = __ldg(av_s + cA + 1);
            float sB0 = __ldg(av_s + cB), sB1 = __ldg(av_s + cB + 1);
            float dA0 = __ldg(av_d + cA), dA1 = __ldg(av_d + cA + 1);
            float dB0 = __ldg(av_d + cB), dB1 = __ldg(av_d + cB + 1);
            float ss0 = acc[2*h][0]*sA0 + acc[2*h][1]*sA1 + acc[2*h+1][0]*sB0 + acc[2*h+1][1]*sB1;
            float sd0 = acc[2*h][0]*dA0 + acc[2*h][1]*dA1 + acc[2*h+1][0]*dB0 + acc[2*h+1][1]*dB1;
            float ss8 = acc[2*h][2]*sA0 + acc[2*h][3]*sA1 + acc[2*h+1][2]*sB0 + acc[2*h+1][3]*sB1;
            float sd8 = acc[2*h][2]*dA0 + acc[2*h][3]*dA1 + acc[2*h+1][2]*dB0 + acc[2*h+1][3]*dB1;
            ss0 += __shfl_xor_sync(0xffffffffu, ss0, 1); ss0 += __shfl_xor_sync(0xffffffffu, ss0, 2);
            sd0 += __shfl_xor_sync(0xffffffffu, sd0, 1); sd0 += __shfl_xor_sync(0xffffffffu, sd0, 2);
            ss8 += __shfl_xor_sync(0xffffffffu, ss8, 1); ss8 += __shfl_xor_sync(0xffffffffu, ss8, 2);
            sd8 += __shfl_xor_sync(0xffffffffu, sd8, 1); sd8 += __shfl_xor_sync(0xffffffffu, sd8, 2);
            if (t == 0) {
                if (r0 < M)     { g_as1[r0 * 8 + h] = ss0;       g_ad1[r0 * 8 + h] = sd0; }
                if (r0 + 8 < M) { g_as1[(r0 + 8) * 8 + h] = ss8; g_ad1[(r0 + 8) * 8 + h] = sd8; }
            }
        }
    } else {
        float ss0 = 0.f, sd0 = 0.f, ss8 = 0.f, sd8 = 0.f;
#pragma unroll
        for (int nb = 0; nb < NB; nb++) {
            int cc = nb * 8 + 2 * t;
            float s0 = __ldg(av_s + cc), s1 = __ldg(av_s + cc + 1);
            float d0 = __ldg(av_d + cc), d1 = __ldg(av_d + cc + 1);
            ss0 += acc[nb][0] * s0 + acc[nb][1] * s1;
            sd0 += acc[nb][0] * d0 + acc[nb][1] * d1;
            ss8 += acc[nb][2] * s0 + acc[nb][3] * s1;
            sd8 += acc[nb][2] * d0 + acc[nb][3] * d1;
        }
        ss0 += __shfl_xor_sync(0xffffffffu, ss0, 1); ss0 += __shfl_xor_sync(0xffffffffu, ss0, 2);
        sd0 += __shfl_xor_sync(0xffffffffu, sd0, 1); sd0 += __shfl_xor_sync(0xffffffffu, sd0, 2);
        ss8 += __shfl_xor_sync(0xffffffffu, ss8, 1); ss8 += __shfl_xor_sync(0xffffffffu, ss8, 2);
        sd8 += __shfl_xor_sync(0xffffffffu, sd8, 1); sd8 += __shfl_xor_sync(0xffffffffu, sd8, 2);
        if (t == 0) {
            if (r0 < M)     { g_as2[r0] = ss0;     g_ad2[r0] = sd0; }
            if (r0 + 8 < M) { g_as2[r0 + 8] = ss8; g_ad2[r0 + 8] = sd8; }
        }
    }
}

// ---------------- layer 1 aggregation: warp per node, 4x pipelined ----------------
// launch_bounds(256,3): guarantee 3 blocks/SM residency -> grid sized to exactly 1 wave.
__global__ void __launch_bounds__(256, 3) agg1_kernel(const float* __restrict__ b1) {
    __shared__ float bsum[128], bssq[128];
    int tid = threadIdx.x;
    if (tid < 128) { bsum[tid] = 0.f; bssq[tid] = 0.f; }
    __syncthreads();

    int lane = tid & 31, wid = tid >> 5;
    int h = lane >> 2, c4 = lane * 4;
    float4 bias = *(const float4*)(b1 + c4);
    float4 psum = make_float4(0.f, 0.f, 0.f, 0.f);
    float4 pssq = make_float4(0.f, 0.f, 0.f, 0.f);

    for (int n = blockIdx.x * 8 + wid; n < NN; n += gridDim.x * 8) {
        float ad_h = __ldg(g_ad1 + n * 8 + h);
        float4 hv = *(const float4*)(g_h1 + (size_t)n * 128 + c4);
        float w = __expf(lrelu(__ldg(g_as1 + n * 8 + h) + ad_h));
        float ax = w * hv.x, ay = w * hv.y, az = w * hv.z, aw = w * hv.w;
        float den = w;
        int beg = g_rowptr[n], end = g_rowptr[n + 1];
        int j = beg;
        for (; j + 3 < end; j += 4) {
            int s0 = __ldg(g_csr + j),     s1 = __ldg(g_csr + j + 1);
            int s2 = __ldg(g_csr + j + 2), s3 = __ldg(g_csr + j + 3);
            float a0 = __ldg(g_as1 + (size_t)s0 * 8 + h);
            float a1 = __ldg(g_as1 + (size_t)s1 * 8 + h);
            float a2 = __ldg(g_as1 + (size_t)s2 * 8 + h);
            float a3 = __ldg(g_as1 + (size_t)s3 * 8 + h);
            float4 h0 = *(const float4*)(g_h1 + (size_t)s0 * 128 + c4);
            float4 h1v = *(const float4*)(g_h1 + (size_t)s1 * 128 + c4);
            float4 h2v = *(const float4*)(g_h1 + (size_t)s2 * 128 + c4);
            float4 h3v = *(const float4*)(g_h1 + (size_t)s3 * 128 + c4);
            float e0 = __expf(lrelu(a0 + ad_h));
            float e1 = __expf(lrelu(a1 + ad_h));
            float e2 = __expf(lrelu(a2 + ad_h));
            float e3 = __expf(lrelu(a3 + ad_h));
            ax += e0 * h0.x + e1 * h1v.x + e2 * h2v.x + e3 * h3v.x;
            ay += e0 * h0.y + e1 * h1v.y + e2 * h2v.y + e3 * h3v.y;
            az += e0 * h0.z + e1 * h1v.z + e2 * h2v.z + e3 * h3v.z;
            aw += e0 * h0.w + e1 * h1v.w + e2 * h2v.w + e3 * h3v.w;
            den += (e0 + e1) + (e2 + e3);
        }
        for (; j < end; j++) {
            int s = __ldg(g_csr + j);
            float ee = __expf(lrelu(__ldg(g_as1 + (size_t)s * 8 + h) + ad_h));
            float4 hs = *(const float4*)(g_h1 + (size_t)s * 128 + c4);
            ax += ee * hs.x; ay += ee * hs.y; az += ee * hs.z; aw += ee * hs.w;
            den += ee;
        }
        float inv = 1.f / den;
        float4 v = make_float4(ax * inv + bias.x, ay * inv + bias.y,
                               az * inv + bias.z, aw * inv + bias.w);
        *(float4*)(g_acc1 + (size_t)n * 128 + c4) = v;
        psum.x += v.x; psum.y += v.y; psum.z += v.z; psum.w += v.w;
        pssq.x += v.x * v.x; pssq.y += v.y * v.y; pssq.z += v.z * v.z; pssq.w += v.w * v.w;
    }

    atomicAdd(&bsum[c4 + 0], psum.x); atomicAdd(&bsum[c4 + 1], psum.y);
    atomicAdd(&bsum[c4 + 2], psum.z); atomicAdd(&bsum[c4 + 3], psum.w);
    atomicAdd(&bssq[c4 + 0], pssq.x); atomicAdd(&bssq[c4 + 1], pssq.y);
    atomicAdd(&bssq[c4 + 2], pssq.z); atomicAdd(&bssq[c4 + 3], pssq.w);
    __syncthreads();
    if (tid < 128) {
        atomicAdd(&g_sum[tid], bsum[tid]);
        atomicAdd(&g_sumsq[tid], bssq[tid]);
    }
}

// ---------------- layer 2 aggregation: warp per node, 8x pipelined ----------------
__global__ void __launch_bounds__(256, 4) agg2_kernel(float* __restrict__ out,
                                                      const float* __restrict__ b2) {
    int tid = threadIdx.x;
    int lane = tid & 31, wid = tid >> 5;
    int c2 = lane * 2;
    float2 bias = *(const float2*)(b2 + c2);

    for (int n = blockIdx.x * 8 + wid; n < NN; n += gridDim.x * 8) {
        float adn = __ldg(g_ad2 + n);
        float2 hv = *(const float2*)(g_h2 + (size_t)n * 64 + c2);
        float w = __expf(lrelu(__ldg(g_as2 + n) + adn));
        float ax = w * hv.x, ay = w * hv.y;
        float den = w;
        int beg = g_rowptr[n], end = g_rowptr[n + 1];
        int j = beg;
        for (; j + 7 < end; j += 8) {
            int s0 = __ldg(g_csr + j),     s1 = __ldg(g_csr + j + 1);
            int s2 = __ldg(g_csr + j + 2), s3 = __ldg(g_csr + j + 3);
            int s4 = __ldg(g_csr + j + 4), s5 = __ldg(g_csr + j + 5);
            int s6 = __ldg(g_csr + j + 6), s7 = __ldg(g_csr + j + 7);
            float a0 = __ldg(g_as2 + s0), a1 = __ldg(g_as2 + s1);
            float a2 = __ldg(g_as2 + s2), a3 = __ldg(g_as2 + s3);
            float a4 = __ldg(g_as2 + s4), a5 = __ldg(g_as2 + s5);
            float a6 = __ldg(g_as2 + s6), a7 = __ldg(g_as2 + s7);
            float2 h0 = *(const float2*)(g_h2 + (size_t)s0 * 64 + c2);
            float2 h1v = *(const float2*)(g_h2 + (size_t)s1 * 64 + c2);
            float2 h2v = *(const float2*)(g_h2 + (size_t)s2 * 64 + c2);
            float2 h3v = *(const float2*)(g_h2 + (size_t)s3 * 64 + c2);
            float2 h4v = *(const float2*)(g_h2 + (size_t)s4 * 64 + c2);
            float2 h5v = *(const float2*)(g_h2 + (size_t)s5 * 64 + c2);
            float2 h6v = *(const float2*)(g_h2 + (size_t)s6 * 64 + c2);
            float2 h7v = *(const float2*)(g_h2 + (size_t)s7 * 64 + c2);
            float e0 = __expf(lrelu(a0 + adn));
            float e1 = __expf(lrelu(a1 + adn));
            float e2 = __expf(lrelu(a2 + adn));
            float e3 = __expf(lrelu(a3 + adn));
            float e4 = __expf(lrelu(a4 + adn));
            float e5 = __expf(lrelu(a5 + adn));
            float e6 = __expf(lrelu(a6 + adn));
            float e7 = __expf(lrelu(a7 + adn));
            ax += e0 * h0.x + e1 * h1v.x + e2 * h2v.x + e3 * h3v.x
                + e4 * h4v.x + e5 * h5v.x + e6 * h6v.x + e7 * h7v.x;
            ay += e0 * h0.y + e1 * h1v.y + e2 * h2v.y + e3 * h3v.y
                + e4 * h4v.y + e5 * h5v.y + e6 * h6v.y + e7 * h7v.y;
            den += ((e0 + e1) + (e2 + e3)) + ((e4 + e5) + (e6 + e7));
        }
        for (; j < end; j++) {
            int s = __ldg(g_csr + j);
            float ee = __expf(lrelu(__ldg(g_as2 + s) + adn));
            float2 hs = *(const float2*)(g_h2 + (size_t)s * 64 + c2);
            ax += ee * hs.x; ay += ee * hs.y;
            den += ee;
        }
        float inv = 1.f / den;
        *(float2*)(out + (size_t)n * 64 + c2) =
            make_float2(ax * inv + bias.x, ay * inv + bias.y);
    }
}

// ---------------- launch ----------------
extern "C" void kernel_launch(void* const* d_in, const int* in_sizes, int n_in,
                              void* d_out, int out_size) {
    // ---- size-driven input resolution (insertion OR alphabetical order) ----
    int iW1 = -1, iW2 = -1, ibig[2] = {-1, -1}, nbig = 0;
    int i128[8], n128 = 0, i64v[8], n64 = 0;
    for (int i = 0; i < n_in; i++) {
        int s = in_sizes[i];
        if (s == 16384)            iW1 = i;
        else if (s == 8192)        iW2 = i;
        else if (s >= 3000000)   { if (nbig < 2) ibig[nbig] = i; nbig++; }
        else if (s == 128)       { if (n128 < 8) i128[n128] = i; n128++; }
        else if (s == 64)        { if (n64  < 8) i64v[n64]  = i; n64++;  }
    }
    const bool insertion = (ibig[0] >= 0 && iW1 >= 0 && ibig[0] < iW1);

    int ix, iei, ia1s, ia1d, ib1, ibng, ibnb, ia2s, ia2d, ib2;
    if (insertion) {
        ix = ibig[0]; iei = ibig[1];
        ia1s = i128[0]; ia1d = i128[1]; ib1 = i128[2]; ibng = i128[3]; ibnb = i128[4];
        ia2s = i64v[0]; ia2d = i64v[1]; ib2 = i64v[2];
    } else {
        iei = ibig[0]; ix = ibig[1];
        ia1d = i128[0]; ia1s = i128[1]; ib1 = i128[2]; ibnb = i128[3]; ibng = i128[4];
        ia2d = i64v[0]; ia2s = i64v[1]; ib2 = i64v[2];
    }
    if (nbig == 2 && in_sizes[ibig[0]] != in_sizes[ibig[1]]) {
        if (in_sizes[iei] > in_sizes[ix]) { int t = ix; ix = iei; iei = t; }
    }

    const float* x    = (const float*)d_in[ix];
    const int*   ei   = (const int*)d_in[iei];
    const float* W1   = (const float*)d_in[iW1];
    const float* a1s  = (const float*)d_in[ia1s];
    const float* a1d  = (const float*)d_in[ia1d];
    const float* b1   = (const float*)d_in[ib1];
    const float* bng  = (const float*)d_in[ibng];
    const float* bnb  = (const float*)d_in[ibnb];
    const float* W2   = (const float*)d_in[iW2];
    const float* a2s  = (const float*)d_in[ia2s];
    const float* a2d  = (const float*)d_in[ia2d];
    const float* b2   = (const float*)d_in[ib2];
    float* out = (float*)d_out;

    const int E = TRUE_E;
    const int T = 256;
    dim3 blk(T);
    const int GEMM_BLOCKS = (NN + 127) / 128;

    // size agg grids to exactly one resident wave
    int smCount = 148;
    cudaDeviceGetAttribute(&smCount, cudaDevAttrMultiProcessorCount, 0);
    int occ1 = 3, occ2 = 4;
    cudaOccupancyMaxActiveBlocksPerMultiprocessor(&occ1, agg1_kernel, T, 0);
    cudaOccupancyMaxActiveBlocksPerMultiprocessor(&occ2, agg2_kernel, T, 0);
    const int AGG1_BLOCKS = smCount * (occ1 > 0 ? occ1 : 3);
    const int AGG2_BLOCKS = smCount * (occ2 > 0 ? occ2 : 4);

    cudaStream_t s2;
    cudaStreamCreate(&s2);
    cudaEvent_t evF, evJ;
    cudaEventCreate(&evF);
    cudaEventCreate(&evJ);

    cudaEventRecord(evF, 0);
    cudaStreamWaitEvent(s2, evF, 0);

    // default stream: CSR chain
    zero_deg_kernel<<<(NN + T - 1) / T, blk>>>(ei);
    count_kernel<<<(E + T - 1) / T, blk>>>(ei, E);
    scan_fused<<<SCAN_B, SCAN_T>>>();
    scatter_kernel<<<(E + T - 1) / T, blk>>>(ei, E);

    // s2: layer-1 GEMM with fused alpha
    sgemm_tc<128, false, 1><<<GEMM_BLOCKS, blk, 0, s2>>>(x, W1, a1s, a1d, nullptr, nullptr, NN, 128);
    cudaEventRecord(evJ, s2);
    cudaStreamWaitEvent(0, evJ, 0);

    // join
    agg1_kernel<<<AGG1_BLOCKS, blk>>>(b1);
    sgemm_tc<64, true, 2><<<GEMM_BLOCKS, blk>>>(nullptr, W2, a2s, a2d, bng, bnb, NN, 128);
    agg2_kernel<<<AGG2_BLOCKS, blk>>>(out, b2);
}

// round 16
// speedup vs baseline: 1.1683x; 1.0011x over previous
#include <cuda_runtime.h>
#include <stdint.h>

#define NN 50000
#define TRUE_E 1600000
#define SCAN_T 1024
#define SCAN_B ((NN + SCAN_T - 1) / SCAN_T)   // 49

// ---------------- scratch (device globals) ----------------
__device__ __align__(16) float g_h1[NN * 128];
__device__ __align__(16) float g_acc1[NN * 128];
__device__ __align__(16) float g_as1[NN * 8];
__device__ __align__(16) float g_ad1[NN * 8];
__device__ __align__(16) float g_sum[128];
__device__ __align__(16) float g_sumsq[128];
__device__ __align__(16) float g_h2[NN * 64];
__device__ __align__(16) float g_as2[NN];
__device__ __align__(16) float g_ad2[NN];
__device__ int g_stride;            // 1 = int32 ids, 2 = int64 ids (lo word)
__device__ int g_done;              // scan inter-block barrier
__device__ int g_deg[NN];
__device__ int g_rowptr[NN + 1];
__device__ int g_bsum[SCAN_B];
__device__ int g_rank[TRUE_E];      // per-edge rank within its dst bucket
__device__ int g_csr[TRUE_E];       // src ids grouped by dst

__device__ __forceinline__ float lrelu(float x) { return fmaxf(x, 0.2f * x); }

__device__ __forceinline__ uint32_t f2tf32(float x) {
    uint32_t u;
    asm("cvt.rna.tf32.f32 %0, %1;" : "=r"(u) : "f"(x));
    return u;
}

__device__ __forceinline__ void mma_tf32(float d[4], uint32_t a0, uint32_t a1,
                                         uint32_t a2, uint32_t a3,
                                         uint32_t b0, uint32_t b1) {
    asm volatile(
        "mma.sync.aligned.m16n8k8.row.col.f32.tf32.tf32.f32 "
        "{%0,%1,%2,%3}, {%4,%5,%6,%7}, {%8,%9}, {%0,%1,%2,%3};"
        : "+f"(d[0]), "+f"(d[1]), "+f"(d[2]), "+f"(d[3])
        : "r"(a0), "r"(a1), "r"(a2), "r"(a3), "r"(b0), "r"(b1));
}

__device__ __forceinline__ void edge_ids(const int* ei, int e, int st, int& s, int& d) {
    s = ei[(size_t)e * st];
    d = ei[(size_t)st * TRUE_E + (size_t)e * st];
}

// ---------------- CSR build ----------------
__global__ void zero_deg_kernel(const int* __restrict__ ei) {
    int n = blockIdx.x * blockDim.x + threadIdx.x;
    if (n < NN) g_deg[n] = 0;
    if (n < 128) { g_sum[n] = 0.f; g_sumsq[n] = 0.f; }
    if (n == 1) g_done = 0;
    if (n == 0) {
        int odd_or = 0;
#pragma unroll
        for (int i = 1; i < 64; i += 2) odd_or |= ei[i];
        g_stride = (odd_or == 0) ? 2 : 1;
    }
}

// count + capture per-edge rank (coalesced store)
__global__ void count_kernel(const int* __restrict__ ei, int E) {
    int e = blockIdx.x * blockDim.x + threadIdx.x;
    if (e >= E) return;
    int st = g_stride;
    int d = ei[(size_t)st * TRUE_E + (size_t)e * st];
    g_rank[e] = atomicAdd(&g_deg[d], 1);
}

// fused two-phase scan: 49 blocks, inter-block spin barrier (all co-resident)
__global__ void scan_fused() {
    __shared__ int sh[SCAN_T];
    __shared__ int s_bsum[SCAN_B];
    __shared__ int s_boff;
    int tid = threadIdx.x;
    int n = blockIdx.x * SCAN_T + tid;
    int v = (n < NN) ? g_deg[n] : 0;
    sh[tid] = v;
    __syncthreads();
    for (int off = 1; off < SCAN_T; off <<= 1) {
        int t = (tid >= off) ? sh[tid - off] : 0;
        __syncthreads();
        sh[tid] += t;
        __syncthreads();
    }
    if (tid == SCAN_T - 1) {
        g_bsum[blockIdx.x] = sh[SCAN_T - 1];
        __threadfence();
        atomicAdd(&g_done, 1);
    }
    if (tid == 0) {
        while (atomicAdd(&g_done, 0) < (int)gridDim.x) { }
    }
    __syncthreads();
    __threadfence();
    if (tid < SCAN_B) s_bsum[tid] = g_bsum[tid];
    __syncthreads();
    if (tid == 0) {
        int run = 0;
        for (int b = 0; b < (int)blockIdx.x; b++) run += s_bsum[b];
        s_boff = run;
        if (blockIdx.x == gridDim.x - 1) {
            int tot = run;
            for (int b = blockIdx.x; b < SCAN_B; b++) tot += s_bsum[b];
            g_rowptr[NN] = tot;
        }
    }
    __syncthreads();
    if (n < NN) g_rowptr[n] = s_boff + sh[tid] - v;
}

// atomic-free scatter: pos = rowptr[d] + rank[e]
__global__ void scatter_kernel(const int* __restrict__ ei, int E) {
    int e = blockIdx.x * blockDim.x + threadIdx.x;
    if (e >= E) return;
    int st = g_stride, s, d;
    edge_ids(ei, e, st, s, d);
    g_csr[g_rowptr[d] + g_rank[e]] = s;
}

// ---------------- tensor-core SGEMM (tf32) + fused alpha epilogue ----------------
template <int BN, bool FUSE_BN, int LAYER>
__global__ void sgemm_tc(const float* __restrict__ Aparam, const float* __restrict__ Bg,
                         const float* __restrict__ av_s, const float* __restrict__ av_d,
                         const float* __restrict__ bng, const float* __restrict__ bnb,
                         int M, int K) {
    const float* __restrict__ A = (LAYER == 1) ? Aparam : (const float*)g_acc1;
    float* __restrict__ C = (LAYER == 1) ? g_h1 : g_h2;

    constexpr int BM = 128, BK = 32;
    constexpr int SA = BK + 4;
    constexpr int SB = BN + 8;
    constexpr int NB = BN / 8;

    __shared__ uint32_t As[BM * SA];
    __shared__ uint32_t Bs[BK * SB];
    __shared__ float s_scale[128], s_shift[128];

    const int tid = threadIdx.x;
    const int lane = tid & 31, warp = tid >> 5;
    const int g = lane >> 2, t = lane & 3;
    const int row0 = blockIdx.x * BM;

    if (FUSE_BN) {
        if (tid < 128) {
            float mu = g_sum[tid] / (float)NN;
            float var = g_sumsq[tid] / (float)NN - mu * mu;
            float rstd = rsqrtf(var + 1e-5f);
            float sc = bng[tid] * rstd;
            s_scale[tid] = sc;
            s_shift[tid] = bnb[tid] - mu * sc;
        }
        __syncthreads();
    }

    float acc[NB][4];
#pragma unroll
    for (int nb = 0; nb < NB; nb++)
#pragma unroll
        for (int q = 0; q < 4; q++) acc[nb][q] = 0.f;

    for (int k0 = 0; k0 < K; k0 += BK) {
#pragma unroll
        for (int f = 0; f < 4; f++) {
            int i = tid + f * 256;
            int r = i >> 3;
            int c4 = (i & 7) * 4;
            float4 v = make_float4(0.f, 0.f, 0.f, 0.f);
            int gr = row0 + r;
            if (gr < M) v = *(const float4*)(A + (size_t)gr * K + k0 + c4);
            if (FUSE_BN) {
                v.x = v.x * s_scale[k0 + c4 + 0] + s_shift[k0 + c4 + 0];
                v.y = v.y * s_scale[k0 + c4 + 1] + s_shift[k0 + c4 + 1];
                v.z = v.z * s_scale[k0 + c4 + 2] + s_shift[k0 + c4 + 2];
                v.w = v.w * s_scale[k0 + c4 + 3] + s_shift[k0 + c4 + 3];
                v.x = v.x > 0.f ? v.x : __expf(v.x) - 1.f;
                v.y = v.y > 0.f ? v.y : __expf(v.y) - 1.f;
                v.z = v.z > 0.f ? v.z : __expf(v.z) - 1.f;
                v.w = v.w > 0.f ? v.w : __expf(v.w) - 1.f;
            }
            uint32_t* p = &As[r * SA + c4];
            p[0] = f2tf32(v.x); p[1] = f2tf32(v.y);
            p[2] = f2tf32(v.z); p[3] = f2tf32(v.w);
        }
        {
            constexpr int BF4 = (BK * BN / 4) / 256;
#pragma unroll
            for (int f = 0; f < BF4; f++) {
                int i = tid + f * 256;
                int r = i / (BN / 4);
                int c4 = (i % (BN / 4)) * 4;
                float4 v = *(const float4*)(Bg + (size_t)(k0 + r) * BN + c4);
                uint32_t* p = &Bs[r * SB + c4];
                p[0] = f2tf32(v.x); p[1] = f2tf32(v.y);
                p[2] = f2tf32(v.z); p[3] = f2tf32(v.w);
            }
        }
        __syncthreads();

#pragma unroll
        for (int k8 = 0; k8 < BK / 8; k8++) {
            int ar = warp * 16 + g;
            uint32_t a0 = As[ar * SA + k8 * 8 + t];
            uint32_t a1 = As[(ar + 8) * SA + k8 * 8 + t];
            uint32_t a2 = As[ar * SA + k8 * 8 + t + 4];
            uint32_t a3 = As[(ar + 8) * SA + k8 * 8 + t + 4];
#pragma unroll
            for (int nb = 0; nb < NB; nb++) {
                uint32_t b0 = Bs[(k8 * 8 + t) * SB + nb * 8 + g];
                uint32_t b1 = Bs[(k8 * 8 + t + 4) * SB + nb * 8 + g];
                mma_tf32(acc[nb], a0, a1, a2, a3, b0, b1);
            }
        }
        __syncthreads();
    }

    int r0 = row0 + warp * 16 + g;
#pragma unroll
    for (int nb = 0; nb < NB; nb++) {
        int cc = nb * 8 + 2 * t;
        if (r0 < M)
            *(float2*)(C + (size_t)r0 * BN + cc) = make_float2(acc[nb][0], acc[nb][1]);
        if (r0 + 8 < M)
            *(float2*)(C + (size_t)(r0 + 8) * BN + cc) = make_float2(acc[nb][2], acc[nb][3]);
    }

    if (LAYER == 1) {
#pragma unroll
        for (int h = 0; h < 8; h++) {
            int cA = 16 * h + 2 * t;
            int cB = cA + 8;
            float sA0 = __ldg(av_s + cA), sA1 = __ldg(av_s + cA + 1);
            float sB0 = __ldg(av_s + cB), sB1 = __ldg(av_s + cB + 1);
            float dA0 = __ldg(av_d + cA), dA1 = __ldg(av_d + cA + 1);
            float dB0 = __ldg(av_d + cB), dB1 = __ldg(av_d + cB + 1);
            float ss0 = acc[2*h][0]*sA0 + acc[2*h][1]*sA1 + acc[2*h+1][0]*sB0 + acc[2*h+1][1]*sB1;
            float sd0 = acc[2*h][0]*dA0 + acc[2*h][1]*dA1 + acc[2*h+1][0]*dB0 + acc[2*h+1][1]*dB1;
            float ss8 = acc[2*h][2]*sA0 + acc[2*h][3]*sA1 + acc[2*h+1][2]*sB0 + acc[2*h+1][3]*sB1;
            float sd8 = acc[2*h][2]*dA0 + acc[2*h][3]*dA1 + acc[2*h+1][2]*dB0 + acc[2*h+1][3]*dB1;
            ss0 += __shfl_xor_sync(0xffffffffu, ss0, 1); ss0 += __shfl_xor_sync(0xffffffffu, ss0, 2);
            sd0 += __shfl_xor_sync(0xffffffffu, sd0, 1); sd0 += __shfl_xor_sync(0xffffffffu, sd0, 2);
            ss8 += __shfl_xor_sync(0xffffffffu, ss8, 1); ss8 += __shfl_xor_sync(0xffffffffu, ss8, 2);
            sd8 += __shfl_xor_sync(0xffffffffu, sd8, 1); sd8 += __shfl_xor_sync(0xffffffffu, sd8, 2);
            if (t == 0) {
                if (r0 < M)     { g_as1[r0 * 8 + h] = ss0;       g_ad1[r0 * 8 + h] = sd0; }
                if (r0 + 8 < M) { g_as1[(r0 + 8) * 8 + h] = ss8; g_ad1[(r0 + 8) * 8 + h] = sd8; }
            }
        }
    } else {
        float ss0 = 0.f, sd0 = 0.f, ss8 = 0.f, sd8 = 0.f;
#pragma unroll
        for (int nb = 0; nb < NB; nb++) {
            int cc = nb * 8 + 2 * t;
            float s0 = __ldg(av_s + cc), s1 = __ldg(av_s + cc + 1);
            float d0 = __ldg(av_d + cc), d1 = __ldg(av_d + cc + 1);
            ss0 += acc[nb][0] * s0 + acc[nb][1] * s1;
            sd0 += acc[nb][0] * d0 + acc[nb][1] * d1;
            ss8 += acc[nb][2] * s0 + acc[nb][3] * s1;
            sd8 += acc[nb][2] * d0 + acc[nb][3] * d1;
        }
        ss0 += __shfl_xor_sync(0xffffffffu, ss0, 1); ss0 += __shfl_xor_sync(0xffffffffu, ss0, 2);
        sd0 += __shfl_xor_sync(0xffffffffu, sd0, 1); sd0 += __shfl_xor_sync(0xffffffffu, sd0, 2);
        ss8 += __shfl_xor_sync(0xffffffffu, ss8, 1); ss8 += __shfl_xor_sync(0xffffffffu, ss8, 2);
        sd8 += __shfl_xor_sync(0xffffffffu, sd8, 1); sd8 += __shfl_xor_sync(0xffffffffu, sd8, 2);
        if (t == 0) {
            if (r0 < M)     { g_as2[r0] = ss0;     g_ad2[r0] = sd0; }
            if (r0 + 8 < M) { g_as2[r0 + 8] = ss8; g_ad2[r0 + 8] = sd8; }
        }
    }
}

// ---------------- layer 1 aggregation: warp per node, 4x pipelined, 1 wave ----------------
__global__ void __launch_bounds__(256, 3) agg1_kernel(const float* __restrict__ b1) {
    __shared__ float bsum[128], bssq[128];
    int tid = threadIdx.x;
    if (tid < 128) { bsum[tid] = 0.f; bssq[tid] = 0.f; }
    __syncthreads();

    int lane = tid & 31, wid = tid >> 5;
    int h = lane >> 2, c4 = lane * 4;
    float4 bias = *(const float4*)(b1 + c4);
    float4 psum = make_float4(0.f, 0.f, 0.f, 0.f);
    float4 pssq = make_float4(0.f, 0.f, 0.f, 0.f);

    for (int n = blockIdx.x * 8 + wid; n < NN; n += gridDim.x * 8) {
        float ad_h = __ldg(g_ad1 + n * 8 + h);
        float4 hv = *(const float4*)(g_h1 + (size_t)n * 128 + c4);
        float w = __expf(lrelu(__ldg(g_as1 + n * 8 + h) + ad_h));
        float ax = w * hv.x, ay = w * hv.y, az = w * hv.z, aw = w * hv.w;
        float den = w;
        int beg = g_rowptr[n], end = g_rowptr[n + 1];
        int j = beg;
        for (; j + 3 < end; j += 4) {
            int s0 = __ldg(g_csr + j),     s1 = __ldg(g_csr + j + 1);
            int s2 = __ldg(g_csr + j + 2), s3 = __ldg(g_csr + j + 3);
            float a0 = __ldg(g_as1 + (size_t)s0 * 8 + h);
            float a1 = __ldg(g_as1 + (size_t)s1 * 8 + h);
            float a2 = __ldg(g_as1 + (size_t)s2 * 8 + h);
            float a3 = __ldg(g_as1 + (size_t)s3 * 8 + h);
            float4 h0 = *(const float4*)(g_h1 + (size_t)s0 * 128 + c4);
            float4 h1v = *(const float4*)(g_h1 + (size_t)s1 * 128 + c4);
            float4 h2v = *(const float4*)(g_h1 + (size_t)s2 * 128 + c4);
            float4 h3v = *(const float4*)(g_h1 + (size_t)s3 * 128 + c4);
            float e0 = __expf(lrelu(a0 + ad_h));
            float e1 = __expf(lrelu(a1 + ad_h));
            float e2 = __expf(lrelu(a2 + ad_h));
            float e3 = __expf(lrelu(a3 + ad_h));
            ax += e0 * h0.x + e1 * h1v.x + e2 * h2v.x + e3 * h3v.x;
            ay += e0 * h0.y + e1 * h1v.y + e2 * h2v.y + e3 * h3v.y;
            az += e0 * h0.z + e1 * h1v.z + e2 * h2v.z + e3 * h3v.z;
            aw += e0 * h0.w + e1 * h1v.w + e2 * h2v.w + e3 * h3v.w;
            den += (e0 + e1) + (e2 + e3);
        }
        for (; j < end; j++) {
            int s = __ldg(g_csr + j);
            float ee = __expf(lrelu(__ldg(g_as1 + (size_t)s * 8 + h) + ad_h));
            float4 hs = *(const float4*)(g_h1 + (size_t)s * 128 + c4);
            ax += ee * hs.x; ay += ee * hs.y; az += ee * hs.z; aw += ee * hs.w;
            den += ee;
        }
        float inv = 1.f / den;
        float4 v = make_float4(ax * inv + bias.x, ay * inv + bias.y,
                               az * inv + bias.z, aw * inv + bias.w);
        *(float4*)(g_acc1 + (size_t)n * 128 + c4) = v;
        psum.x += v.x; psum.y += v.y; psum.z += v.z; psum.w += v.w;
        pssq.x += v.x * v.x; pssq.y += v.y * v.y; pssq.z += v.z * v.z; pssq.w += v.w * v.w;
    }

    atomicAdd(&bsum[c4 + 0], psum.x); atomicAdd(&bsum[c4 + 1], psum.y);
    atomicAdd(&bsum[c4 + 2], psum.z); atomicAdd(&bsum[c4 + 3], psum.w);
    atomicAdd(&bssq[c4 + 0], pssq.x); atomicAdd(&bssq[c4 + 1], pssq.y);
    atomicAdd(&bssq[c4 + 2], pssq.z); atomicAdd(&bssq[c4 + 3], pssq.w);
    __syncthreads();
    if (tid < 128) {
        atomicAdd(&g_sum[tid], bsum[tid]);
        atomicAdd(&g_sumsq[tid], bssq[tid]);
    }
}

// ---------------- layer 2 aggregation: warp per node, 8x pipelined, 1 wave ----------------
__global__ void __launch_bounds__(256, 4) agg2_kernel(float* __restrict__ out,
                                                      const float* __restrict__ b2) {
    int tid = threadIdx.x;
    int lane = tid & 31, wid = tid >> 5;
    int c2 = lane * 2;
    float2 bias = *(const float2*)(b2 + c2);

    for (int n = blockIdx.x * 8 + wid; n < NN; n += gridDim.x * 8) {
        float adn = __ldg(g_ad2 + n);
        float2 hv = *(const float2*)(g_h2 + (size_t)n * 64 + c2);
        float w = __expf(lrelu(__ldg(g_as2 + n) + adn));
        float ax = w * hv.x, ay = w * hv.y;
        float den = w;
        int beg = g_rowptr[n], end = g_rowptr[n + 1];
        int j = beg;
        for (; j + 7 < end; j += 8) {
            int s0 = __ldg(g_csr + j),     s1 = __ldg(g_csr + j + 1);
            int s2 = __ldg(g_csr + j + 2), s3 = __ldg(g_csr + j + 3);
            int s4 = __ldg(g_csr + j + 4), s5 = __ldg(g_csr + j + 5);
            int s6 = __ldg(g_csr + j + 6), s7 = __ldg(g_csr + j + 7);
            float a0 = __ldg(g_as2 + s0), a1 = __ldg(g_as2 + s1);
            float a2 = __ldg(g_as2 + s2), a3 = __ldg(g_as2 + s3);
            float a4 = __ldg(g_as2 + s4), a5 = __ldg(g_as2 + s5);
            float a6 = __ldg(g_as2 + s6), a7 = __ldg(g_as2 + s7);
            float2 h0 = *(const float2*)(g_h2 + (size_t)s0 * 64 + c2);
            float2 h1v = *(const float2*)(g_h2 + (size_t)s1 * 64 + c2);
            float2 h2v = *(const float2*)(g_h2 + (size_t)s2 * 64 + c2);
            float2 h3v = *(const float2*)(g_h2 + (size_t)s3 * 64 + c2);
            float2 h4v = *(const float2*)(g_h2 + (size_t)s4 * 64 + c2);
            float2 h5v = *(const float2*)(g_h2 + (size_t)s5 * 64 + c2);
            float2 h6v = *(const float2*)(g_h2 + (size_t)s6 * 64 + c2);
            float2 h7v = *(const float2*)(g_h2 + (size_t)s7 * 64 + c2);
            float e0 = __expf(lrelu(a0 + adn));
            float e1 = __expf(lrelu(a1 + adn));
            float e2 = __expf(lrelu(a2 + adn));
            float e3 = __expf(lrelu(a3 + adn));
            float e4 = __expf(lrelu(a4 + adn));
            float e5 = __expf(lrelu(a5 + adn));
            float e6 = __expf(lrelu(a6 + adn));
            float e7 = __expf(lrelu(a7 + adn));
            ax += e0 * h0.x + e1 * h1v.x + e2 * h2v.x + e3 * h3v.x
                + e4 * h4v.x + e5 * h5v.x + e6 * h6v.x + e7 * h7v.x;
            ay += e0 * h0.y + e1 * h1v.y + e2 * h2v.y + e3 * h3v.y
                + e4 * h4v.y + e5 * h5v.y + e6 * h6v.y + e7 * h7v.y;
            den += ((e0 + e1) + (e2 + e3)) + ((e4 + e5) + (e6 + e7));
        }
        for (; j < end; j++) {
            int s = __ldg(g_csr + j);
            float ee = __expf(lrelu(__ldg(g_as2 + s) + adn));
            float2 hs = *(const float2*)(g_h2 + (size_t)s * 64 + c2);
            ax += ee * hs.x; ay += ee * hs.y;
            den += ee;
        }
        float inv = 1.f / den;
        *(float2*)(out + (size_t)n * 64 + c2) =
            make_float2(ax * inv + bias.x, ay * inv + bias.y);
    }
}

// ---------------- launch ----------------
extern "C" void kernel_launch(void* const* d_in, const int* in_sizes, int n_in,
                              void* d_out, int out_size) {
    // ---- size-driven input resolution (insertion OR alphabetical order) ----
    int iW1 = -1, iW2 = -1, ibig[2] = {-1, -1}, nbig = 0;
    int i128[8], n128 = 0, i64v[8], n64 = 0;
    for (int i = 0; i < n_in; i++) {
        int s = in_sizes[i];
        if (s == 16384)            iW1 = i;
        else if (s == 8192)        iW2 = i;
        else if (s >= 3000000)   { if (nbig < 2) ibig[nbig] = i; nbig++; }
        else if (s == 128)       { if (n128 < 8) i128[n128] = i; n128++; }
        else if (s == 64)        { if (n64  < 8) i64v[n64]  = i; n64++;  }
    }
    const bool insertion = (ibig[0] >= 0 && iW1 >= 0 && ibig[0] < iW1);

    int ix, iei, ia1s, ia1d, ib1, ibng, ibnb, ia2s, ia2d, ib2;
    if (insertion) {
        ix = ibig[0]; iei = ibig[1];
        ia1s = i128[0]; ia1d = i128[1]; ib1 = i128[2]; ibng = i128[3]; ibnb = i128[4];
        ia2s = i64v[0]; ia2d = i64v[1]; ib2 = i64v[2];
    } else {
        iei = ibig[0]; ix = ibig[1];
        ia1d = i128[0]; ia1s = i128[1]; ib1 = i128[2]; ibnb = i128[3]; ibng = i128[4];
        ia2d = i64v[0]; ia2s = i64v[1]; ib2 = i64v[2];
    }
    if (nbig == 2 && in_sizes[ibig[0]] != in_sizes[ibig[1]]) {
        if (in_sizes[iei] > in_sizes[ix]) { int t = ix; ix = iei; iei = t; }
    }

    const float* x    = (const float*)d_in[ix];
    const int*   ei   = (const int*)d_in[iei];
    const float* W1   = (const float*)d_in[iW1];
    const float* a1s  = (const float*)d_in[ia1s];
    const float* a1d  = (const float*)d_in[ia1d];
    const float* b1   = (const float*)d_in[ib1];
    const float* bng  = (const float*)d_in[ibng];
    const float* bnb  = (const float*)d_in[ibnb];
    const float* W2   = (const float*)d_in[iW2];
    const float* a2s  = (const float*)d_in[ia2s];
    const float* a2d  = (const float*)d_in[ia2d];
    const float* b2   = (const float*)d_in[ib2];
    float* out = (float*)d_out;

    const int E = TRUE_E;
    const int T = 256;
    dim3 blk(T);
    const int GEMM_BLOCKS = (NN + 127) / 128;

    int smCount = 148;
    cudaDeviceGetAttribute(&smCount, cudaDevAttrMultiProcessorCount, 0);
    int occ1 = 3, occ2 = 4;
    cudaOccupancyMaxActiveBlocksPerMultiprocessor(&occ1, agg1_kernel, T, 0);
    cudaOccupancyMaxActiveBlocksPerMultiprocessor(&occ2, agg2_kernel, T, 0);
    const int AGG1_BLOCKS = smCount * (occ1 > 0 ? occ1 : 3);
    const int AGG2_BLOCKS = smCount * (occ2 > 0 ? occ2 : 4);

    cudaStream_t s2;
    cudaStreamCreate(&s2);
    cudaEvent_t evF, evJ;
    cudaEventCreate(&evF);
    cudaEventCreate(&evJ);

    cudaEventRecord(evF, 0);
    cudaStreamWaitEvent(s2, evF, 0);

    // default stream: CSR chain
    zero_deg_kernel<<<(NN + T - 1) / T, blk>>>(ei);
    count_kernel<<<(E + T - 1) / T, blk>>>(ei, E);
    scan_fused<<<SCAN_B, SCAN_T>>>();
    scatter_kernel<<<(E + T - 1) / T, blk>>>(ei, E);

    // s2: layer-1 GEMM with fused alpha
    sgemm_tc<128, false, 1><<<GEMM_BLOCKS, blk, 0, s2>>>(x, W1, a1s, a1d, nullptr, nullptr, NN, 128);
    cudaEventRecord(evJ, s2);
    cudaStreamWaitEvent(0, evJ, 0);

    // join
    agg1_kernel<<<AGG1_BLOCKS, blk>>>(b1);
    sgemm_tc<64, true, 2><<<GEMM_BLOCKS, blk>>>(nullptr, W2, a2s, a2d, bng, bnb, NN, 128);
    agg2_kernel<<<AGG2_BLOCKS, blk>>>(out, b2);
}